// round 1
// baseline (speedup 1.0000x reference)
#include <cuda_runtime.h>
#include <math.h>

#define NN 200000
#define NE 800000
#define NG 8192
#define HD 200
#define NLAYERS 5
#define TSTEPS 2

// ------------------------- scratch (static device globals) -------------------------
__device__ float d_h[(size_t)NN * HD];
__device__ float d_e[(size_t)NE * HD];
__device__ float d_agg[(size_t)NN * HD];
__device__ float d_hv[(size_t)NN * HD];
__device__ float d_g[NG * HD];
__device__ float d_ctx[NG * HD];
__device__ float d_gi[NG * 600];
__device__ float d_gh[NG * 600];
__device__ float d_t1[NG * 1024];
__device__ float d_z[NN];
__device__ float d_aw[NN];
__device__ float d_zmax[NG];
__device__ float d_zden[NG];
__device__ int d_cnt[NN];
__device__ int d_rowptr[NN + 1];
__device__ int d_fill[NN];
__device__ int2 d_adj[NE];
__device__ int d_gcnt[NG];
__device__ int d_gptr[NG + 1];
__device__ int d_bsums[1024];

// ------------------------- small utility kernels -------------------------
__global__ void zero_int(int* p, int n) {
    int gid = blockIdx.x * blockDim.x + threadIdx.x;
    if (gid < n) p[gid] = 0;
}

__global__ void hist_kernel(const int* __restrict__ idx, int* __restrict__ cnt, int n) {
    int gid = blockIdx.x * blockDim.x + threadIdx.x;
    if (gid < n) atomicAdd(&cnt[idx[gid]], 1);
}

// block scan: each block handles 8192 items (1024 thr x 8). writes inclusive scan into out[i+1].
__global__ void scan1_kernel(const int* __restrict__ in, int* __restrict__ outp1,
                             int* __restrict__ bsums, int n) {
    __shared__ int sh[1024];
    int t = threadIdx.x;
    long base = (long)blockIdx.x * 8192 + (long)t * 8;
    int v[8];
    int run = 0;
#pragma unroll
    for (int i = 0; i < 8; i++) {
        long idx = base + i;
        int x = (idx < n) ? in[idx] : 0;
        run += x;
        v[i] = run;
    }
    sh[t] = run;
    __syncthreads();
    int total = run;
    for (int off = 1; off < 1024; off <<= 1) {
        int y = (t >= off) ? sh[t - off] : 0;
        __syncthreads();
        sh[t] += y;
        __syncthreads();
    }
    int excl = sh[t] - total;
#pragma unroll
    for (int i = 0; i < 8; i++) {
        long idx = base + i;
        if (idx < n) outp1[idx + 1] = v[i] + excl;
    }
    if (t == 1023) bsums[blockIdx.x] = sh[1023];
    if (blockIdx.x == 0 && t == 0) outp1[0] = 0;
}

__global__ void scan2_kernel(int* bsums, int nb) {
    __shared__ int sh[1024];
    int t = threadIdx.x;
    int v = (t < nb) ? bsums[t] : 0;
    sh[t] = v;
    __syncthreads();
    for (int off = 1; off < 1024; off <<= 1) {
        int y = (t >= off) ? sh[t - off] : 0;
        __syncthreads();
        sh[t] += y;
        __syncthreads();
    }
    if (t < nb) bsums[t] = sh[t] - v;  // exclusive
}

__global__ void scan3_kernel(int* outp1, const int* __restrict__ bsums, int n) {
    int gid = blockIdx.x * blockDim.x + threadIdx.x;
    if (gid < n) outp1[gid + 1] += bsums[gid >> 13];
}

__global__ void copy_int(const int* __restrict__ a, int* __restrict__ b, int n) {
    int gid = blockIdx.x * blockDim.x + threadIdx.x;
    if (gid < n) b[gid] = a[gid];
}

__global__ void fill_adj_kernel(const int* __restrict__ src, const int* __restrict__ dst,
                                int* __restrict__ fill, int2* __restrict__ adj, int n) {
    int gid = blockIdx.x * blockDim.x + threadIdx.x;
    if (gid < n) {
        int d = dst[gid];
        int pos = atomicAdd(&fill[d], 1);
        adj[pos] = make_int2(src[gid], gid);
    }
}

// ------------------------- generic tiled fp32 GEMM -------------------------
// C[M, NCOL] = epilogue( A[M,K] @ W[K,NCOL(ldw)] + bias )
// mode 0: C = acc + bias
// mode 1: C = relu(acc + bias) * ls[col] + C   (residual in-place)
#define BM 64
#define BN 224
#define BK 40

__global__ __launch_bounds__(256) void gemm_kernel(
    const float* __restrict__ A, const float* __restrict__ W,
    const float* __restrict__ bias, float* __restrict__ C,
    int M, int K, int NCOL, int ldw, int ldc, int mode, const float* __restrict__ ls) {
    __shared__ float Ast[BK][BM + 1];
    __shared__ float Ws[BK][BN];
    int tid = threadIdx.x;
    int mt = tid >> 5;   // 0..7
    int nt = tid & 31;   // 0..31
    int row0 = blockIdx.x * BM;
    int col0 = blockIdx.y * BN;

    float acc[8][7];
#pragma unroll
    for (int i = 0; i < 8; i++)
#pragma unroll
        for (int j = 0; j < 7; j++) acc[i][j] = 0.f;

    for (int k0 = 0; k0 < K; k0 += BK) {
        int bk = min(BK, K - k0);
        // load A tile (transposed into smem)
        for (int idx = tid; idx < BM * bk; idx += 256) {
            int r = idx / bk;
            int kk = idx - r * bk;
            int gr = row0 + r;
            Ast[kk][r] = (gr < M) ? A[(long)gr * K + k0 + kk] : 0.f;
        }
        // load W tile
        for (int idx = tid; idx < bk * BN; idx += 256) {
            int kk = idx / BN;
            int cc = idx - kk * BN;
            int gc = col0 + cc;
            Ws[kk][cc] = (gc < NCOL) ? W[(long)(k0 + kk) * ldw + gc] : 0.f;
        }
        __syncthreads();
        if (bk == BK) {
#pragma unroll 2
            for (int kk = 0; kk < BK; kk++) {
                float a[8], w[7];
#pragma unroll
                for (int i = 0; i < 8; i++) a[i] = Ast[kk][mt + 8 * i];
#pragma unroll
                for (int j = 0; j < 7; j++) w[j] = Ws[kk][nt + 32 * j];
#pragma unroll
                for (int i = 0; i < 8; i++)
#pragma unroll
                    for (int j = 0; j < 7; j++) acc[i][j] = fmaf(a[i], w[j], acc[i][j]);
            }
        } else {
            for (int kk = 0; kk < bk; kk++) {
                float a[8], w[7];
#pragma unroll
                for (int i = 0; i < 8; i++) a[i] = Ast[kk][mt + 8 * i];
#pragma unroll
                for (int j = 0; j < 7; j++) w[j] = Ws[kk][nt + 32 * j];
#pragma unroll
                for (int i = 0; i < 8; i++)
#pragma unroll
                    for (int j = 0; j < 7; j++) acc[i][j] = fmaf(a[i], w[j], acc[i][j]);
            }
        }
        __syncthreads();
    }
#pragma unroll
    for (int i = 0; i < 8; i++) {
        int gr = row0 + mt + 8 * i;
        if (gr >= M) continue;
#pragma unroll
        for (int j = 0; j < 7; j++) {
            int gc = col0 + nt + 32 * j;
            if (gc >= NCOL) continue;
            float v = acc[i][j] + (bias ? bias[gc] : 0.f);
            long off = (long)gr * ldc + gc;
            if (mode == 1) v = fmaxf(v, 0.f) * ls[gc] + C[off];
            C[off] = v;
        }
    }
}

// ------------------------- message passing: fused gather + edge softmax + agg -------------------------
__global__ void msg_kernel(const float* __restrict__ h, const float* __restrict__ e,
                           const int* __restrict__ rowptr, const int2* __restrict__ adj,
                           float* __restrict__ agg) {
    long gid = (long)blockIdx.x * blockDim.x + threadIdx.x;
    if (gid >= (long)NN * HD) return;
    int v = (int)(gid / HD);
    int f = (int)(gid - (long)v * HD);
    int b = rowptr[v], en = rowptr[v + 1];
    float mx = -3.4e38f, den = 0.f, acc = 0.f;
    for (int p = b; p < en; p++) {
        int2 se = adj[p];
        float m = h[(long)se.x * HD + f] + e[(long)se.y * HD + f];
        if (m > mx) {
            float sc = __expf(mx - m);
            den *= sc;
            acc *= sc;
            mx = m;
        }
        float pz = __expf(m - mx);
        den += pz;
        acc += pz * m;
    }
    agg[gid] = (den > 0.f) ? acc / den : 0.f;
}

// ------------------------- graph readout kernels -------------------------
__global__ void gsum_kernel(const float* __restrict__ h, const int* __restrict__ gptr,
                            float* __restrict__ g) {
    int gid = blockIdx.x * blockDim.x + threadIdx.x;
    if (gid >= NG * HD) return;
    int gg = gid / HD;
    int f = gid - gg * HD;
    int b = gptr[gg], e = gptr[gg + 1];
    float s = 0.f;
    for (int n = b; n < e; n++) s += h[(long)n * HD + f];
    g[gid] = s;
}

__global__ void z_kernel(const float* __restrict__ h, const float* __restrict__ g,
                         const int* __restrict__ n2g, const float* __restrict__ lw,
                         const float* __restrict__ lb, float* __restrict__ z) {
    int warp = (blockIdx.x * blockDim.x + threadIdx.x) >> 5;
    int lane = threadIdx.x & 31;
    if (warp >= NN) return;
    int gg = n2g[warp];
    const float* grow = g + (long)gg * HD;
    const float* hrow = h + (long)warp * HD;
    float s = 0.f;
    for (int f = lane; f < HD; f += 32)
        s += fmaxf(grow[f], 0.f) * lw[f] + hrow[f] * lw[HD + f];
#pragma unroll
    for (int o = 16; o; o >>= 1) s += __shfl_xor_sync(0xffffffffu, s, o);
    if (lane == 0) {
        float v = s + lb[0];
        z[warp] = (v > 0.f) ? v : 0.01f * v;  // leaky_relu
    }
}

__global__ void attn_kernel(const float* __restrict__ z, const int* __restrict__ gptr,
                            float* __restrict__ zmax, float* __restrict__ zden) {
    int warp = (blockIdx.x * blockDim.x + threadIdx.x) >> 5;
    int lane = threadIdx.x & 31;
    if (warp >= NG) return;
    int b = gptr[warp], e = gptr[warp + 1];
    float mx = -3.4e38f;
    for (int i = b + lane; i < e; i += 32) mx = fmaxf(mx, z[i]);
#pragma unroll
    for (int o = 16; o; o >>= 1) mx = fmaxf(mx, __shfl_xor_sync(0xffffffffu, mx, o));
    float s = 0.f;
    for (int i = b + lane; i < e; i += 32) s += __expf(z[i] - mx);
#pragma unroll
    for (int o = 16; o; o >>= 1) s += __shfl_xor_sync(0xffffffffu, s, o);
    if (lane == 0) {
        zmax[warp] = mx;
        zden[warp] = s;
    }
}

__global__ void a_kernel(const float* __restrict__ z, const int* __restrict__ n2g,
                         const float* __restrict__ zmax, const float* __restrict__ zden,
                         float* __restrict__ a) {
    int gid = blockIdx.x * blockDim.x + threadIdx.x;
    if (gid >= NN) return;
    int gg = n2g[gid];
    a[gid] = __expf(z[gid] - zmax[gg]) / zden[gg];
}

__global__ void ctx_kernel(const float* __restrict__ hv, const float* __restrict__ a,
                           const int* __restrict__ gptr, float* __restrict__ ctx) {
    int gid = blockIdx.x * blockDim.x + threadIdx.x;
    if (gid >= NG * HD) return;
    int gg = gid / HD;
    int f = gid - gg * HD;
    int b = gptr[gg], e = gptr[gg + 1];
    float s = 0.f;
    for (int n = b; n < e; n++) s += hv[(long)n * HD + f] * a[n];
    ctx[gid] = (s > 0.f) ? s : (__expf(s) - 1.f);  // elu
}

__global__ void gru_kernel(const float* __restrict__ gi, const float* __restrict__ gh,
                           float* __restrict__ g) {
    int gid = blockIdx.x * blockDim.x + threadIdx.x;
    if (gid >= NG * HD) return;
    int gg = gid / HD;
    int f = gid - gg * HD;
    const float* gib = gi + gg * 600;
    const float* ghb = gh + gg * 600;
    float r = 1.f / (1.f + __expf(-(gib[f] + ghb[f])));
    float u = 1.f / (1.f + __expf(-(gib[200 + f] + ghb[200 + f])));
    float nn = tanhf(gib[400 + f] + r * ghb[400 + f]);
    g[gid] = (1.f - u) * nn + u * g[gid];
}

__global__ void out2_kernel(const float* __restrict__ tmp, const float* __restrict__ w2,
                            const float* __restrict__ b2, float* __restrict__ out) {
    int warp = (blockIdx.x * blockDim.x + threadIdx.x) >> 5;
    int lane = threadIdx.x & 31;
    if (warp >= NG) return;
    float s = 0.f;
    const float* row = tmp + (long)warp * 1024;
    for (int c = lane; c < 1024; c += 32) s += fmaxf(row[c], 0.f) * w2[c];
#pragma unroll
    for (int o = 16; o; o >>= 1) s += __shfl_xor_sync(0xffffffffu, s, o);
    if (lane == 0) out[warp] = s + b2[0];
}

// ------------------------- launch -------------------------
extern "C" void kernel_launch(void* const* d_in, const int* in_sizes, int n_in,
                              void* d_out, int out_size) {
    const float* node_feats = (const float*)d_in[0];
    const float* edge_feats = (const float*)d_in[1];
    const int* src = (const int*)d_in[2];
    const int* dst = (const int*)d_in[3];
    const int* n2g = (const int*)d_in[4];
    const float* atom_W = (const float*)d_in[5];
    const float* atom_b = (const float*)d_in[6];
    const float* bond_W = (const float*)d_in[7];
    const float* bond_b = (const float*)d_in[8];
    const float* mlp_W = (const float*)d_in[9];
    const float* mlp_b = (const float*)d_in[10];
    const float* ls = (const float*)d_in[11];
    const float* logit_W = (const float*)d_in[12];
    const float* logit_b = (const float*)d_in[13];
    const float* proj_W = (const float*)d_in[14];
    const float* proj_b = (const float*)d_in[15];
    const float* gru_Wih = (const float*)d_in[16];
    const float* gru_Whh = (const float*)d_in[17];
    const float* gru_bih = (const float*)d_in[18];
    const float* gru_bhh = (const float*)d_in[19];
    const float* out1_W = (const float*)d_in[20];
    const float* out1_b = (const float*)d_in[21];
    const float* out2_W = (const float*)d_in[22];
    const float* out2_b = (const float*)d_in[23];
    float* out = (float*)d_out;

    float *ph, *pe, *pagg, *phv, *pg, *pctx, *pgi, *pgh, *pt1, *pz, *paw, *pzmax, *pzden;
    int *pcnt, *prow, *pfill, *pgcnt, *pgptr, *pbs;
    int2* padj;
    cudaGetSymbolAddress((void**)&ph, d_h);
    cudaGetSymbolAddress((void**)&pe, d_e);
    cudaGetSymbolAddress((void**)&pagg, d_agg);
    cudaGetSymbolAddress((void**)&phv, d_hv);
    cudaGetSymbolAddress((void**)&pg, d_g);
    cudaGetSymbolAddress((void**)&pctx, d_ctx);
    cudaGetSymbolAddress((void**)&pgi, d_gi);
    cudaGetSymbolAddress((void**)&pgh, d_gh);
    cudaGetSymbolAddress((void**)&pt1, d_t1);
    cudaGetSymbolAddress((void**)&pz, d_z);
    cudaGetSymbolAddress((void**)&paw, d_aw);
    cudaGetSymbolAddress((void**)&pzmax, d_zmax);
    cudaGetSymbolAddress((void**)&pzden, d_zden);
    cudaGetSymbolAddress((void**)&pcnt, d_cnt);
    cudaGetSymbolAddress((void**)&prow, d_rowptr);
    cudaGetSymbolAddress((void**)&pfill, d_fill);
    cudaGetSymbolAddress((void**)&pgcnt, d_gcnt);
    cudaGetSymbolAddress((void**)&pgptr, d_gptr);
    cudaGetSymbolAddress((void**)&pbs, d_bsums);
    cudaGetSymbolAddress((void**)&padj, d_adj);

    // ---- CSR by dst ----
    zero_int<<<(NN + 255) / 256, 256>>>(pcnt, NN);
    hist_kernel<<<(NE + 255) / 256, 256>>>(dst, pcnt, NE);
    int nb1 = (NN + 8191) / 8192;
    scan1_kernel<<<nb1, 1024>>>(pcnt, prow, pbs, NN);
    scan2_kernel<<<1, 1024>>>(pbs, nb1);
    scan3_kernel<<<(NN + 255) / 256, 256>>>(prow, pbs, NN);
    copy_int<<<(NN + 255) / 256, 256>>>(prow, pfill, NN);
    fill_adj_kernel<<<(NE + 255) / 256, 256>>>(src, dst, pfill, padj, NE);

    // ---- graph offsets (node2graph is sorted; use histogram+scan for robustness) ----
    zero_int<<<(NG + 255) / 256, 256>>>(pgcnt, NG);
    hist_kernel<<<(NN + 255) / 256, 256>>>(n2g, pgcnt, NN);
    scan1_kernel<<<1, 1024>>>(pgcnt, pgptr, pbs, NG);
    scan2_kernel<<<1, 1024>>>(pbs, 1);
    scan3_kernel<<<(NG + 255) / 256, 256>>>(pgptr, pbs, NG);

    // ---- encoders ----
    dim3 gN((NN + BM - 1) / BM, 1);
    dim3 gE((NE + BM - 1) / BM, 1);
    gemm_kernel<<<gN, 256>>>(node_feats, atom_W, atom_b, ph, NN, 74, HD, HD, HD, 0, nullptr);
    gemm_kernel<<<gE, 256>>>(edge_feats, bond_W, bond_b, pe, NE, 12, HD, HD, HD, 0, nullptr);

    // ---- message passing layers ----
    long nthr = (long)NN * HD;
    int mblocks = (int)((nthr + 255) / 256);
    for (int i = 0; i < NLAYERS; i++) {
        msg_kernel<<<mblocks, 256>>>(ph, pe, prow, padj, pagg);
        gemm_kernel<<<gN, 256>>>(pagg, mlp_W + (size_t)i * HD * HD, mlp_b + i * HD, ph,
                                 NN, HD, HD, HD, HD, 1, ls + i * HD);
    }

    // ---- readout ----
    gsum_kernel<<<(NG * HD + 255) / 256, 256>>>(ph, pgptr, pg);
    for (int t = 0; t < TSTEPS; t++) {
        z_kernel<<<(NN * 32 + 255) / 256, 256>>>(ph, pg, n2g, logit_W + t * 2 * HD,
                                                 logit_b + t, pz);
        attn_kernel<<<(NG * 32 + 255) / 256, 256>>>(pz, pgptr, pzmax, pzden);
        a_kernel<<<(NN + 255) / 256, 256>>>(pz, n2g, pzmax, pzden, paw);
        gemm_kernel<<<gN, 256>>>(ph, proj_W + (size_t)t * HD * HD, proj_b + t * HD, phv,
                                 NN, HD, HD, HD, HD, 0, nullptr);
        ctx_kernel<<<(NG * HD + 255) / 256, 256>>>(phv, paw, pgptr, pctx);
        dim3 gG((NG + BM - 1) / BM, (600 + BN - 1) / BN);
        gemm_kernel<<<gG, 256>>>(pctx, gru_Wih + (size_t)t * HD * 600, gru_bih + t * 600,
                                 pgi, NG, HD, 600, 600, 600, 0, nullptr);
        gemm_kernel<<<gG, 256>>>(pg, gru_Whh + (size_t)t * HD * 600, gru_bhh + t * 600,
                                 pgh, NG, HD, 600, 600, 600, 0, nullptr);
        gru_kernel<<<(NG * HD + 255) / 256, 256>>>(pgi, pgh, pg);
    }

    dim3 gO((NG + BM - 1) / BM, (1024 + BN - 1) / BN);
    gemm_kernel<<<gO, 256>>>(pg, out1_W, out1_b, pt1, NG, HD, 1024, 1024, 1024, 0, nullptr);
    out2_kernel<<<(NG * 32 + 255) / 256, 256>>>(pt1, out2_W, out2_b, out);
}